// round 16
// baseline (speedup 1.0000x reference)
#include <cuda_runtime.h>
#include <cstdint>
#include <cstddef>

#define NN 4096
#define MM 4096
#define DD 1024
// k = int(4096*4096*0.3) = 5033164 ; ascending 0-based rank = 16777216 - k
#define RANK_ASC 11744052u
#define NB 32          // DP column chunks
#define CW 128         // columns per chunk
#define TBR 448        // traceback tile rows
#define NG (NN / 4)    // handoff groups (4 rows each)

// ---------------- static device scratch (no allocations allowed) ----------------
__device__ float    g_z[(size_t)NN * DD];
__device__ float    g_x[(size_t)MM * DD];
__device__ float    g_sim[(size_t)NN * MM];
// decision bytes: g_dec[block*NN*32 + row*32 + (localcol/4)]
//   bit s   = diag(col 4*(localcol/4)+s), bit 4+s = up
__device__ unsigned char g_dec[(size_t)NN * 1024];
// boundary handoff, 4 rows per float4: g_bound2[b*NG + g] = D[4g+1..4g+4][b*CW]
__device__ float4   g_bound2[(size_t)NB * NG];
__device__ unsigned g_hist[256];
__device__ unsigned g_sel[2];   // [0]=prefix key, [1]=remaining rank
__device__ float    g_dropline;

// ---------------- helpers ----------------
__device__ __forceinline__ unsigned fkey(float f) {
    unsigned u = __float_as_uint(f);
    return (u & 0x80000000u) ? ~u : (u | 0x80000000u);
}
// volatile (strong) 128-bit handoff ops — single instruction each.
__device__ __forceinline__ float4 ldv4(const float4* p) {
    float4 v;
    asm volatile("ld.volatile.global.v4.f32 {%0,%1,%2,%3}, [%4];"
                 : "=f"(v.x), "=f"(v.y), "=f"(v.z), "=f"(v.w) : "l"(p));
    return v;
}
__device__ __forceinline__ void stv4(float4* p, float4 v) {
    asm volatile("st.volatile.global.v4.f32 [%0], {%1,%2,%3,%4};"
                 :: "l"(p), "f"(v.x), "f"(v.y), "f"(v.z), "f"(v.w));
}

// ---------------- init (must reset all mutable state every replay) ----------------
__global__ void init_state() {
    int idx = blockIdx.x * blockDim.x + threadIdx.x;
    if (idx < 256) g_hist[idx] = 0u;
    if (idx == 0) { g_sel[0] = 0u; g_sel[1] = RANK_ASC; }
    int total = NB * NG;
    float4 s; s.x = s.y = s.z = s.w = 1.0f;   // sentinel: real D values are <= 0
    for (int i = idx; i < total; i += gridDim.x * blockDim.x)
        g_bound2[i] = s;
}

__global__ void fill_zero4(float4* __restrict__ out, size_t n4) {
    size_t stride = (size_t)gridDim.x * blockDim.x;
    float4 z; z.x = z.y = z.z = z.w = 0.f;
    for (size_t i = blockIdx.x * (size_t)blockDim.x + threadIdx.x; i < n4; i += stride)
        out[i] = z;
}

// ---------------- row normalize ----------------
__global__ void normalize_rows(const float* __restrict__ in, int which) {
    int row = blockIdx.x;
    int t = threadIdx.x;                 // 256 threads
    const float* p = in + (size_t)row * DD;
    float s = 0.f;
#pragma unroll
    for (int k = 0; k < 4; k++) { float v = p[t + k * 256]; s = fmaf(v, v, s); }
    __shared__ float red[256];
    red[t] = s; __syncthreads();
    for (int o = 128; o > 0; o >>= 1) { if (t < o) red[t] += red[t + o]; __syncthreads(); }
    float nrm = sqrtf(red[0]);
    float* q = (which == 0 ? g_z : g_x) + (size_t)row * DD;
#pragma unroll
    for (int k = 0; k < 4; k++) q[t + k * 256] = p[t + k * 256] / nrm;
}

// ---------------- f32 NT GEMM: 256x128 block tile, 16x8 thread tile, BK=8 ----------------
// Accumulation order per output element identical (ascending k, per-component
// IEEE fma) => bitwise-identical sim.
__global__ void __launch_bounds__(256, 1) gemm_nt() {
    __shared__ __align__(16) float As[2][8][260];
    __shared__ __align__(16) float Bs[2][8][132];
    int tid = threadIdx.x;
    int ty = tid >> 4;   // 0..15 -> 16 output rows each
    int tx = tid & 15;   // 0..15 -> 8 output cols each
    int bi = blockIdx.y * 256;
    int bj = blockIdx.x * 128;

    unsigned long long acc2[8][8];
#pragma unroll
    for (int rp = 0; rp < 8; rp++)
#pragma unroll
        for (int c = 0; c < 8; c++) acc2[rp][c] = 0ull;

    int brow = tid & 127;
    int bk4 = (tid >> 7) * 4;

    {
        float4 va0 = *reinterpret_cast<const float4*>(&g_z[(size_t)(bi + tid) * DD + 0]);
        float4 va1 = *reinterpret_cast<const float4*>(&g_z[(size_t)(bi + tid) * DD + 4]);
        float4 vb0 = *reinterpret_cast<const float4*>(&g_x[(size_t)(bj + brow) * DD + bk4]);
        As[0][0][tid] = va0.x; As[0][1][tid] = va0.y;
        As[0][2][tid] = va0.z; As[0][3][tid] = va0.w;
        As[0][4][tid] = va1.x; As[0][5][tid] = va1.y;
        As[0][6][tid] = va1.z; As[0][7][tid] = va1.w;
        Bs[0][bk4 + 0][brow] = vb0.x; Bs[0][bk4 + 1][brow] = vb0.y;
        Bs[0][bk4 + 2][brow] = vb0.z; Bs[0][bk4 + 3][brow] = vb0.w;
    }
    __syncthreads();

    int s = 0;
    for (int k0 = 0; k0 < DD; k0 += 8, s ^= 1) {
        float4 va0, va1, vb0;
        bool more = (k0 + 8 < DD);
        if (more) {
            int kn = k0 + 8;
            va0 = *reinterpret_cast<const float4*>(&g_z[(size_t)(bi + tid) * DD + kn]);
            va1 = *reinterpret_cast<const float4*>(&g_z[(size_t)(bi + tid) * DD + kn + 4]);
            vb0 = *reinterpret_cast<const float4*>(&g_x[(size_t)(bj + brow) * DD + kn + bk4]);
        }
#pragma unroll
        for (int kk = 0; kk < 8; kk++) {
            const ulonglong2* ap2 = reinterpret_cast<const ulonglong2*>(&As[s][kk][ty * 16]);
            ulonglong2 aa = ap2[0], ab = ap2[1], ac = ap2[2], ad = ap2[3];
            unsigned long long a2[8];
            a2[0] = aa.x; a2[1] = aa.y; a2[2] = ab.x; a2[3] = ab.y;
            a2[4] = ac.x; a2[5] = ac.y; a2[6] = ad.x; a2[7] = ad.y;
            const float4* bp = reinterpret_cast<const float4*>(&Bs[s][kk][tx * 8]);
            float4 b0 = bp[0], b1 = bp[1];
            float bbv[8];
            bbv[0] = b0.x; bbv[1] = b0.y; bbv[2] = b0.z; bbv[3] = b0.w;
            bbv[4] = b1.x; bbv[5] = b1.y; bbv[6] = b1.z; bbv[7] = b1.w;
            unsigned long long b2[8];
#pragma unroll
            for (int c = 0; c < 8; c++)
                asm("mov.b64 %0, {%1, %1};" : "=l"(b2[c]) : "r"(__float_as_uint(bbv[c])));
#pragma unroll
            for (int c = 0; c < 8; c++)
#pragma unroll
                for (int rp = 0; rp < 8; rp++)
                    asm("fma.rn.f32x2 %0, %1, %2, %0;"
                        : "+l"(acc2[rp][c]) : "l"(a2[rp]), "l"(b2[c]));
        }
        __syncthreads();
        if (more) {
            int d = s ^ 1;
            As[d][0][tid] = va0.x; As[d][1][tid] = va0.y;
            As[d][2][tid] = va0.z; As[d][3][tid] = va0.w;
            As[d][4][tid] = va1.x; As[d][5][tid] = va1.y;
            As[d][6][tid] = va1.z; As[d][7][tid] = va1.w;
            Bs[d][bk4 + 0][brow] = vb0.x; Bs[d][bk4 + 1][brow] = vb0.y;
            Bs[d][bk4 + 2][brow] = vb0.z; Bs[d][bk4 + 3][brow] = vb0.w;
            __syncthreads();
        }
    }
#pragma unroll
    for (int rp = 0; rp < 8; rp++) {
        float lo[8], hi[8];
#pragma unroll
        for (int c = 0; c < 8; c++) {
            lo[c] = __uint_as_float((unsigned)(acc2[rp][c] & 0xffffffffull));
            hi[c] = __uint_as_float((unsigned)(acc2[rp][c] >> 32));
        }
        float* dst0 = &g_sim[(size_t)(bi + ty * 16 + 2 * rp) * MM + (bj + tx * 8)];
        float* dst1 = &g_sim[(size_t)(bi + ty * 16 + 2 * rp + 1) * MM + (bj + tx * 8)];
        float4 o;
        o.x = lo[0]; o.y = lo[1]; o.z = lo[2]; o.w = lo[3];
        *reinterpret_cast<float4*>(dst0) = o;
        o.x = lo[4]; o.y = lo[5]; o.z = lo[6]; o.w = lo[7];
        *reinterpret_cast<float4*>(dst0 + 4) = o;
        o.x = hi[0]; o.y = hi[1]; o.z = hi[2]; o.w = hi[3];
        *reinterpret_cast<float4*>(dst1) = o;
        o.x = hi[4]; o.y = hi[5]; o.z = hi[6]; o.w = hi[7];
        *reinterpret_cast<float4*>(dst1 + 4) = o;
    }
}

// ---------------- exact radix select (privatized per-warp hists) ----------------
__global__ void hist_pass(int shift) {
    __shared__ unsigned sh[8][256];
    int t = threadIdx.x;
    int wid = t >> 5;
    for (int k = t; k < 8 * 256; k += 256) ((unsigned*)sh)[k] = 0u;
    __syncthreads();
    unsigned prefix = g_sel[0];
    int above = shift + 8;
    size_t stride = (size_t)gridDim.x * blockDim.x;
    size_t total = (size_t)NN * MM;
    for (size_t i = blockIdx.x * (size_t)blockDim.x + threadIdx.x; i < total; i += stride) {
        unsigned u = fkey(g_sim[i]);
        bool ok = (above >= 32) || ((u >> above) == (prefix >> above));
        if (ok) atomicAdd(&sh[wid][(u >> shift) & 255u], 1u);
    }
    __syncthreads();
    unsigned tot = 0;
#pragma unroll
    for (int wq = 0; wq < 8; wq++) tot += sh[wq][t];
    if (tot) atomicAdd(&g_hist[t], tot);
}

__global__ void select_pass(int shift, int last) {
    __shared__ unsigned cnt[256];
    int t = threadIdx.x;
    cnt[t] = g_hist[t];
    g_hist[t] = 0u;   // reset for the next pass
    __syncthreads();
    if (t == 0) {
        unsigned rank = g_sel[1], cum = 0; int bin = 255;
        for (int b = 0; b < 256; b++) {
            unsigned c = cnt[b];
            if (cum + c > rank) { bin = b; break; }
            cum += c;
        }
        g_sel[0] |= ((unsigned)bin) << shift;
        g_sel[1] = rank - cum;
        if (last) {
            unsigned u = g_sel[0];
            unsigned bits = (u & 0x80000000u) ? (u & 0x7FFFFFFFu) : ~u;
            g_dropline = __uint_as_float(bits);
        }
    }
}

// ---------------- NW DP wavefront: 8 cols/lane x 16 lanes, 4-shuffle scan,
// ---------------- volatile 4-row-batched handoff with early peek ----------------
// All quantities are exact mins over the same sets as before (tree==chain for
// fminf) and the base-carry identity holds per lane => decisions bit-identical.
#define DP_MASK 0x0000FFFFu

__device__ __forceinline__ float dp_row8(
    int lane, int i, float dropline, float4 lo, float4 hi, float incoming,
    float* prev, float& bcar, unsigned short* decp)
{
    float sim[8];
    sim[0] = lo.x; sim[1] = lo.y; sim[2] = lo.z; sim[3] = lo.w;
    sim[4] = hi.x; sim[5] = hi.y; sim[6] = hi.z; sim[7] = hi.w;
    float cc[8], d[8], n[8];
#pragma unroll
    for (int k = 0; k < 8; k++) cc[k] = dropline - sim[k];
    d[0] = bcar + cc[0];                 // left neighbor = previous row's base (exact identity)
#pragma unroll
    for (int k = 1; k < 8; k++) d[k] = prev[k - 1] + cc[k];
#pragma unroll
    for (int k = 0; k < 8; k++) n[k] = fminf(d[k], prev[k]);

    // lane-total via tree (depth 3) -> feeds scan early
    float t01 = fminf(n[0], n[1]), t23 = fminf(n[2], n[3]);
    float t45 = fminf(n[4], n[5]), t67 = fminf(n[6], n[7]);
    float t03 = fminf(t01, t23), t47 = fminf(t45, t67);
    float T = fminf(t03, t47);

    // 16-lane inclusive min-scan (4 shuffles) + exclusive prefix
    float S = T;
#pragma unroll
    for (int o = 1; o < 16; o <<= 1) {
        float v = __shfl_up_sync(DP_MASK, S, o);
        if (lane >= o) S = fminf(S, v);
    }
    float E = __shfl_up_sync(DP_MASK, S, 1);

    // in-lane prefix (computed in parallel with the scan; exact min-sets)
    float p[8];
    p[0] = n[0]; p[1] = t01; p[2] = fminf(t01, n[2]); p[3] = t03;
    p[4] = fminf(t03, n[4]); p[5] = fminf(t03, t45); p[6] = fminf(p[5], n[6]); p[7] = T;

    float nbase = (lane == 0) ? incoming : fminf(incoming, E);
    float D[8];
#pragma unroll
    for (int k = 0; k < 8; k++) D[k] = fminf(nbase, p[k]);

    unsigned bits = 0;
#pragma unroll
    for (int k = 0; k < 8; k++) {
        bool df = (D[k] == d[k]);
        bool uf = (!df) && (D[k] == prev[k]);
        int sh = ((k >> 2) << 3) + (k & 3);
        bits |= (df ? 1u : 0u) << sh;
        bits |= (uf ? 1u : 0u) << (sh + 4);
    }
    decp[(size_t)(i - 1) * 16] = (unsigned short)bits;   // byte = localcol/4 layout preserved

#pragma unroll
    for (int k = 0; k < 8; k++) prev[k] = D[k];
    bcar = nbase;
    return D[7];
}

__device__ __forceinline__ bool inc_ready(float4 v) {
    return !(v.x > 0.5f || v.y > 0.5f || v.z > 0.5f || v.w > 0.5f);
}

__global__ void __launch_bounds__(32, 1) dp_kernel(int rows) {   // rows % 4 == 0
    const int b = blockIdx.x;
    const int lane = threadIdx.x;
    if (lane >= 16) return;              // 16 active lanes, 8 cols each
    const int c0 = b * CW;
    const float dropline = g_dropline;
    const float* gsim = g_sim + c0 + 8 * lane;
    unsigned short* decp = (unsigned short*)(g_dec + (size_t)b * NN * 32) + lane;
    const float4* bnd = &g_bound2[(size_t)b * NG];

    float prev[8];
#pragma unroll
    for (int k = 0; k < 8; k++) prev[k] = 0.f;
    float bcar = 0.f;   // D[0][...] row is all zeros

    int ng = rows >> 2;
    // preload group 0's sim rows (4 rows x 8 floats)
    float4 sl[4], sh[4];
#pragma unroll
    for (int r = 0; r < 4; r++) {
        sl[r] = *reinterpret_cast<const float4*>(gsim + (size_t)r * MM);
        sh[r] = *reinterpret_cast<const float4*>(gsim + (size_t)r * MM + 4);
    }

    // incoming for group 0
    float4 inc4; inc4.x = inc4.y = inc4.z = inc4.w = 0.f;
    if (b != 0) {
        inc4 = ldv4(bnd);
        while (!inc_ready(inc4)) inc4 = ldv4(bnd);
    }

    for (int g = 0; g < ng; ++g) {
        float4 nl[4], nh[4];
        if (g + 1 < ng) {   // prefetch next group's sim rows
            const float* nb2 = gsim + (size_t)(4 * (g + 1)) * MM;
#pragma unroll
            for (int r = 0; r < 4; r++) {
                nl[r] = *reinterpret_cast<const float4*>(nb2 + (size_t)r * MM);
                nh[r] = *reinterpret_cast<const float4*>(nb2 + (size_t)r * MM + 4);
            }
        }
        int i = 4 * g + 1;
        float4 out4;
        out4.x = dp_row8(lane, i + 0, dropline, sl[0], sh[0], inc4.x, prev, bcar, decp);
        out4.y = dp_row8(lane, i + 1, dropline, sl[1], sh[1], inc4.y, prev, bcar, decp);
        out4.z = dp_row8(lane, i + 2, dropline, sl[2], sh[2], inc4.z, prev, bcar, decp);
        out4.w = dp_row8(lane, i + 3, dropline, sl[3], sh[3], inc4.w, prev, bcar, decp);

        // early peek for group g+1 BEFORE the publish store
        float4 nxt; nxt.x = nxt.y = nxt.z = nxt.w = 0.f;
        const float4* pp = bnd + (g + 1);
        bool need = (b != 0) && (g + 1 < ng);
        if (need) nxt = ldv4(pp);

        if (lane == 15 && b < NB - 1)
            stv4(&g_bound2[(size_t)(b + 1) * NG + g], out4);

        if (need) { while (!inc_ready(nxt)) nxt = ldv4(pp); }
        inc4 = nxt;
#pragma unroll
        for (int r = 0; r < 4; r++) { sl[r] = nl[r]; sh[r] = nh[r]; }
    }
}

// ---------------- traceback: 448-row tiles, u64 nibble repack, left-run skipping ----------------
__device__ __forceinline__ unsigned nib_compact(unsigned long long x) {
    x &= 0x0F0F0F0F0F0F0F0Full;
    x = (x | (x >> 4))  & 0x00FF00FF00FF00FFull;
    x = (x | (x >> 8))  & 0x0000FFFF0000FFFFull;
    x = (x | (x >> 16));
    return (unsigned)x;
}

__global__ void traceback(float* __restrict__ out) {
    __shared__ uint2    s_du[TBR * 8];
    __shared__ unsigned s_c[TBR * 8];
    __shared__ int s_ij[2];
    int t = threadIdx.x;    // 256 threads
    int i = NN, j = MM;
    while (i > 0 && j > 0) {
        int ilo = (i - (TBR - 1) > 1) ? (i - (TBR - 1)) : 1;
        int jbhi = (j - 1) >> 7;                       // 128-col strip of current jj
        int jblo = (jbhi - 1 > 0) ? (jbhi - 1) : 0;    // stage 2 strips
        int rows = i - ilo + 1;
        for (int idx = t; idx < rows * 8; idx += 256) {
            int r = idx >> 3, wq = idx & 7;            // natural word 0..7 across 2 strips
            int strip = jblo + (wq >> 2), w4 = wq & 3;
            size_t boff = (size_t)strip * ((size_t)NN * 32)
                        + (size_t)(ilo - 1 + r) * 32 + (size_t)w4 * 8;
            unsigned long long Bv = *reinterpret_cast<const unsigned long long*>(&g_dec[boff]);
            unsigned dw = nib_compact(Bv);
            unsigned uw = nib_compact(Bv >> 4);
            s_du[r * 8 + wq] = make_uint2(dw, uw);
            s_c[r * 8 + wq] = dw | uw;
        }
        __syncthreads();
        if (t == 0) {
            int jlo = jblo * 128 + 1;                  // smallest j inside the staged strips
            while (i >= ilo && j >= jlo) {
                int jj = j - 1;
                int r = i - ilo;
                int w = (jj >> 5) - jblo * 4;          // 0..7
                int bit = jj & 31;
                uint2 du = s_du[r * 8 + w];
                if ((du.x >> bit) & 1u) {
                    out[(size_t)(i - 1) * MM + jj] = 1.0f; --i; --j;
                } else if ((du.y >> bit) & 1u) {
                    --i;
                } else {
                    unsigned m = s_c[r * 8 + w] & ((bit == 0) ? 0u : ((1u << bit) - 1u));
                    for (;;) {
                        if (m) { int nb = 31 - __clz(m); j = (jblo * 4 + w) * 32 + nb + 1; break; }
                        if (w == 0) { j = jlo - 1; break; }
                        --w;
                        m = s_c[r * 8 + w];
                    }
                }
            }
            s_ij[0] = i; s_ij[1] = j;
        }
        __syncthreads();
        i = s_ij[0]; j = s_ij[1];
        __syncthreads();
    }
}

// ---------------- launch ----------------
extern "C" void kernel_launch(void* const* d_in, const int* in_sizes, int n_in,
                              void* d_out, int out_size) {
    (void)in_sizes; (void)n_in; (void)out_size;
    const float* text  = (const float*)d_in[2];
    const float* event = (const float*)d_in[3];
    float* out = (float*)d_out;

    // gemm_nt is launch #4 for ncu (-s 5 -c 1 + 2 harness launches).
    init_state<<<256, 256>>>();
    normalize_rows<<<NN, 256>>>(text, 0);
    normalize_rows<<<MM, 256>>>(event, 1);
    gemm_nt<<<dim3(32, 16), 256>>>();
    for (int p = 0; p < 4; ++p) {
        int shift = 24 - 8 * p;
        hist_pass<<<2048, 256>>>(shift);
        select_pass<<<1, 256>>>(shift, p == 3 ? 1 : 0);
    }
    fill_zero4<<<2048, 256>>>((float4*)out, (size_t)NN * MM / 4);
    dp_kernel<<<NB, 32>>>(NN);
    traceback<<<1, 256>>>(out);
}

// round 17
// speedup vs baseline: 1.1942x; 1.1942x over previous
#include <cuda_runtime.h>
#include <cstdint>
#include <cstddef>

#define NN 4096
#define MM 4096
#define DD 1024
// k = int(4096*4096*0.3) = 5033164 ; ascending 0-based rank = 16777216 - k
#define RANK_ASC 11744052u
#define NB 32          // DP column chunks
#define CW 128         // columns per chunk
#define TBR 448        // traceback tile rows
#define NG (NN / 4)    // boundary quads (4 rows each)

// ---------------- static device scratch (no allocations allowed) ----------------
__device__ float    g_z[(size_t)NN * DD];
__device__ float    g_x[(size_t)MM * DD];
__device__ float    g_sim[(size_t)NN * MM];
// decision bytes, coalesced per block: g_dec[block*NN*32 + row*32 + lane]
__device__ unsigned char g_dec[(size_t)NN * 1024];
// boundary handoff, 4 rows per float4: g_bound2[b*NG + g] = D[4g+1..4g+4][b*CW]
__device__ float4   g_bound2[(size_t)NB * NG];
__device__ unsigned g_hist[256];
__device__ unsigned g_sel[2];   // [0]=prefix key, [1]=remaining rank
__device__ float    g_dropline;

// ---------------- helpers ----------------
__device__ __forceinline__ unsigned fkey(float f) {
    unsigned u = __float_as_uint(f);
    return (u & 0x80000000u) ? ~u : (u | 0x80000000u);
}
// volatile (strong) 128-bit handoff ops — single instruction each.
__device__ __forceinline__ float4 ldv4(const float4* p) {
    float4 v;
    asm volatile("ld.volatile.global.v4.f32 {%0,%1,%2,%3}, [%4];"
                 : "=f"(v.x), "=f"(v.y), "=f"(v.z), "=f"(v.w) : "l"(p));
    return v;
}
__device__ __forceinline__ void stv4(float4* p, float4 v) {
    asm volatile("st.volatile.global.v4.f32 [%0], {%1,%2,%3,%4};"
                 :: "l"(p), "f"(v.x), "f"(v.y), "f"(v.z), "f"(v.w));
}

// ---------------- init (must reset all mutable state every replay) ----------------
__global__ void init_state() {
    int idx = blockIdx.x * blockDim.x + threadIdx.x;
    if (idx < 256) g_hist[idx] = 0u;
    if (idx == 0) { g_sel[0] = 0u; g_sel[1] = RANK_ASC; }
    int total = NB * NG;
    float4 s; s.x = s.y = s.z = s.w = 1.0f;   // sentinel: real D values are <= 0
    for (int i = idx; i < total; i += gridDim.x * blockDim.x)
        g_bound2[i] = s;
}

__global__ void fill_zero4(float4* __restrict__ out, size_t n4) {
    size_t stride = (size_t)gridDim.x * blockDim.x;
    float4 z; z.x = z.y = z.z = z.w = 0.f;
    for (size_t i = blockIdx.x * (size_t)blockDim.x + threadIdx.x; i < n4; i += stride)
        out[i] = z;
}

// ---------------- row normalize ----------------
__global__ void normalize_rows(const float* __restrict__ in, int which) {
    int row = blockIdx.x;
    int t = threadIdx.x;                 // 256 threads
    const float* p = in + (size_t)row * DD;
    float s = 0.f;
#pragma unroll
    for (int k = 0; k < 4; k++) { float v = p[t + k * 256]; s = fmaf(v, v, s); }
    __shared__ float red[256];
    red[t] = s; __syncthreads();
    for (int o = 128; o > 0; o >>= 1) { if (t < o) red[t] += red[t + o]; __syncthreads(); }
    float nrm = sqrtf(red[0]);
    float* q = (which == 0 ? g_z : g_x) + (size_t)row * DD;
#pragma unroll
    for (int k = 0; k < 4; k++) q[t + k * 256] = p[t + k * 256] / nrm;
}

// ---------------- f32 NT GEMM: 256x128 block tile, 16x8 thread tile, BK=8 ----------------
// Accumulation order per output element identical (ascending k, per-component
// IEEE fma) => bitwise-identical sim.
__global__ void __launch_bounds__(256, 1) gemm_nt() {
    __shared__ __align__(16) float As[2][8][260];
    __shared__ __align__(16) float Bs[2][8][132];
    int tid = threadIdx.x;
    int ty = tid >> 4;   // 0..15 -> 16 output rows each
    int tx = tid & 15;   // 0..15 -> 8 output cols each
    int bi = blockIdx.y * 256;
    int bj = blockIdx.x * 128;

    unsigned long long acc2[8][8];
#pragma unroll
    for (int rp = 0; rp < 8; rp++)
#pragma unroll
        for (int c = 0; c < 8; c++) acc2[rp][c] = 0ull;

    int brow = tid & 127;
    int bk4 = (tid >> 7) * 4;

    {
        float4 va0 = *reinterpret_cast<const float4*>(&g_z[(size_t)(bi + tid) * DD + 0]);
        float4 va1 = *reinterpret_cast<const float4*>(&g_z[(size_t)(bi + tid) * DD + 4]);
        float4 vb0 = *reinterpret_cast<const float4*>(&g_x[(size_t)(bj + brow) * DD + bk4]);
        As[0][0][tid] = va0.x; As[0][1][tid] = va0.y;
        As[0][2][tid] = va0.z; As[0][3][tid] = va0.w;
        As[0][4][tid] = va1.x; As[0][5][tid] = va1.y;
        As[0][6][tid] = va1.z; As[0][7][tid] = va1.w;
        Bs[0][bk4 + 0][brow] = vb0.x; Bs[0][bk4 + 1][brow] = vb0.y;
        Bs[0][bk4 + 2][brow] = vb0.z; Bs[0][bk4 + 3][brow] = vb0.w;
    }
    __syncthreads();

    int s = 0;
    for (int k0 = 0; k0 < DD; k0 += 8, s ^= 1) {
        float4 va0, va1, vb0;
        bool more = (k0 + 8 < DD);
        if (more) {
            int kn = k0 + 8;
            va0 = *reinterpret_cast<const float4*>(&g_z[(size_t)(bi + tid) * DD + kn]);
            va1 = *reinterpret_cast<const float4*>(&g_z[(size_t)(bi + tid) * DD + kn + 4]);
            vb0 = *reinterpret_cast<const float4*>(&g_x[(size_t)(bj + brow) * DD + kn + bk4]);
        }
#pragma unroll
        for (int kk = 0; kk < 8; kk++) {
            const ulonglong2* ap2 = reinterpret_cast<const ulonglong2*>(&As[s][kk][ty * 16]);
            ulonglong2 aa = ap2[0], ab = ap2[1], ac = ap2[2], ad = ap2[3];
            unsigned long long a2[8];
            a2[0] = aa.x; a2[1] = aa.y; a2[2] = ab.x; a2[3] = ab.y;
            a2[4] = ac.x; a2[5] = ac.y; a2[6] = ad.x; a2[7] = ad.y;
            const float4* bp = reinterpret_cast<const float4*>(&Bs[s][kk][tx * 8]);
            float4 b0 = bp[0], b1 = bp[1];
            float bbv[8];
            bbv[0] = b0.x; bbv[1] = b0.y; bbv[2] = b0.z; bbv[3] = b0.w;
            bbv[4] = b1.x; bbv[5] = b1.y; bbv[6] = b1.z; bbv[7] = b1.w;
            unsigned long long b2[8];
#pragma unroll
            for (int c = 0; c < 8; c++)
                asm("mov.b64 %0, {%1, %1};" : "=l"(b2[c]) : "r"(__float_as_uint(bbv[c])));
#pragma unroll
            for (int c = 0; c < 8; c++)
#pragma unroll
                for (int rp = 0; rp < 8; rp++)
                    asm("fma.rn.f32x2 %0, %1, %2, %0;"
                        : "+l"(acc2[rp][c]) : "l"(a2[rp]), "l"(b2[c]));
        }
        __syncthreads();
        if (more) {
            int d = s ^ 1;
            As[d][0][tid] = va0.x; As[d][1][tid] = va0.y;
            As[d][2][tid] = va0.z; As[d][3][tid] = va0.w;
            As[d][4][tid] = va1.x; As[d][5][tid] = va1.y;
            As[d][6][tid] = va1.z; As[d][7][tid] = va1.w;
            Bs[d][bk4 + 0][brow] = vb0.x; Bs[d][bk4 + 1][brow] = vb0.y;
            Bs[d][bk4 + 2][brow] = vb0.z; Bs[d][bk4 + 3][brow] = vb0.w;
            __syncthreads();
        }
    }
#pragma unroll
    for (int rp = 0; rp < 8; rp++) {
        float lo[8], hi[8];
#pragma unroll
        for (int c = 0; c < 8; c++) {
            lo[c] = __uint_as_float((unsigned)(acc2[rp][c] & 0xffffffffull));
            hi[c] = __uint_as_float((unsigned)(acc2[rp][c] >> 32));
        }
        float* dst0 = &g_sim[(size_t)(bi + ty * 16 + 2 * rp) * MM + (bj + tx * 8)];
        float* dst1 = &g_sim[(size_t)(bi + ty * 16 + 2 * rp + 1) * MM + (bj + tx * 8)];
        float4 o;
        o.x = lo[0]; o.y = lo[1]; o.z = lo[2]; o.w = lo[3];
        *reinterpret_cast<float4*>(dst0) = o;
        o.x = lo[4]; o.y = lo[5]; o.z = lo[6]; o.w = lo[7];
        *reinterpret_cast<float4*>(dst0 + 4) = o;
        o.x = hi[0]; o.y = hi[1]; o.z = hi[2]; o.w = hi[3];
        *reinterpret_cast<float4*>(dst1) = o;
        o.x = hi[4]; o.y = hi[5]; o.z = hi[6]; o.w = hi[7];
        *reinterpret_cast<float4*>(dst1 + 4) = o;
    }
}

// ---------------- exact radix select (privatized per-warp hists) ----------------
__global__ void hist_pass(int shift) {
    __shared__ unsigned sh[8][256];
    int t = threadIdx.x;
    int wid = t >> 5;
    for (int k = t; k < 8 * 256; k += 256) ((unsigned*)sh)[k] = 0u;
    __syncthreads();
    unsigned prefix = g_sel[0];
    int above = shift + 8;
    size_t stride = (size_t)gridDim.x * blockDim.x;
    size_t total = (size_t)NN * MM;
    for (size_t i = blockIdx.x * (size_t)blockDim.x + threadIdx.x; i < total; i += stride) {
        unsigned u = fkey(g_sim[i]);
        bool ok = (above >= 32) || ((u >> above) == (prefix >> above));
        if (ok) atomicAdd(&sh[wid][(u >> shift) & 255u], 1u);
    }
    __syncthreads();
    unsigned tot = 0;
#pragma unroll
    for (int wq = 0; wq < 8; wq++) tot += sh[wq][t];
    if (tot) atomicAdd(&g_hist[t], tot);
}

__global__ void select_pass(int shift, int last) {
    __shared__ unsigned cnt[256];
    int t = threadIdx.x;
    cnt[t] = g_hist[t];
    g_hist[t] = 0u;   // reset for the next pass
    __syncthreads();
    if (t == 0) {
        unsigned rank = g_sel[1], cum = 0; int bin = 255;
        for (int b = 0; b < 256; b++) {
            unsigned c = cnt[b];
            if (cum + c > rank) { bin = b; break; }
            cum += c;
        }
        g_sel[0] |= ((unsigned)bin) << shift;
        g_sel[1] = rank - cum;
        if (last) {
            unsigned u = g_sel[0];
            unsigned bits = (u & 0x80000000u) ? (u & 0x7FFFFFFFu) : ~u;
            g_dropline = __uint_as_float(bits);
        }
    }
}

// ---------------- NW DP wavefront: R14 structure (32 lanes x 4 cols),
// ---------------- 8-row super-groups: wait/publish per quad, peek per super-group ----------------
__device__ __forceinline__ float dp_row(
    int lane, int i, float dropline, float4 simCur, float incoming,
    float& prev0, float& prev1, float& prev2, float& prev3,
    float& bcar, unsigned char* decp)
{
    float cc0 = dropline - simCur.x;
    float cc1 = dropline - simCur.y;
    float cc2 = dropline - simCur.z;
    float cc3 = dropline - simCur.w;

    float d0 = bcar + cc0;     // left neighbor = previous row's base (exact identity)
    float d1 = prev0 + cc1;
    float d2 = prev1 + cc2;
    float d3 = prev2 + cc3;
    float n0 = fminf(d0, prev0);
    float n1 = fminf(d1, prev1);
    float n2 = fminf(d2, prev2);
    float n3 = fminf(d3, prev3);
    float p0 = n0;
    float p1 = fminf(p0, n1);
    float p2 = fminf(p1, n2);
    float p3 = fminf(p2, n3);

    // warp inclusive min-scan, unpredicated (shfl_up out-of-range returns own
    // value; fmin(S,S)=S => bitwise identical to predicated form)
    float S = p3;
#pragma unroll
    for (int o = 1; o < 32; o <<= 1) {
        float v = __shfl_up_sync(0xffffffffu, S, o);
        S = fminf(S, v);
    }
    float E = __shfl_up_sync(0xffffffffu, S, 1);   // exclusive prefix (lanes > 0)

    float nbase = (lane == 0) ? incoming : fminf(incoming, E);
    float D0 = fminf(nbase, p0);
    float D1 = fminf(nbase, p1);
    float D2 = fminf(nbase, p2);
    float D3 = fminf(nbase, p3);

    bool df0 = (D0 == d0); bool uf0 = (!df0) && (D0 == prev0);
    bool df1 = (D1 == d1); bool uf1 = (!df1) && (D1 == prev1);
    bool df2 = (D2 == d2); bool uf2 = (!df2) && (D2 == prev2);
    bool df3 = (D3 == d3); bool uf3 = (!df3) && (D3 == prev3);
    unsigned byte = (df0 ? 1u : 0u) | (df1 ? 2u : 0u) | (df2 ? 4u : 0u) | (df3 ? 8u : 0u)
                  | (uf0 ? 16u : 0u) | (uf1 ? 32u : 0u) | (uf2 ? 64u : 0u) | (uf3 ? 128u : 0u);
    decp[(size_t)(i - 1) * 32] = (unsigned char)byte;   // coalesced: 32B/warp/row

    prev0 = D0; prev1 = D1; prev2 = D2; prev3 = D3;
    bcar = nbase;
    return D3;
}

__device__ __forceinline__ bool inc_ready(float4 v) {
    return !(v.x > 0.5f || v.y > 0.5f || v.z > 0.5f || v.w > 0.5f);
}

__global__ void __launch_bounds__(32, 1) dp_kernel(int rows) {   // rows % 8 == 0
    const int b = blockIdx.x;
    const int lane = threadIdx.x;
    const int c0 = b * CW;
    const float dropline = g_dropline;
    const float* gsim = g_sim + c0 + 4 * lane;
    unsigned char* decp = g_dec + (size_t)b * NN * 32 + lane;
    const float4* bnd = &g_bound2[(size_t)b * NG];

    float prev0 = 0.f, prev1 = 0.f, prev2 = 0.f, prev3 = 0.f;
    float bcar = 0.f;   // D[0][...] row is all zeros

    int nsg = rows >> 3;   // 8-row super-groups
    // preload super-group 0's sim rows
    float4 sv[8];
#pragma unroll
    for (int r = 0; r < 8; r++)
        sv[r] = *reinterpret_cast<const float4*>(gsim + (size_t)r * MM);

    // peeks for super-group 0 (quads 0 and 1)
    float4 pA, pB;
    pA.x = pA.y = pA.z = pA.w = 0.f;
    pB.x = pB.y = pB.z = pB.w = 0.f;
    if (b != 0) { pA = ldv4(bnd + 0); pB = ldv4(bnd + 1); }

    for (int sg = 0; sg < nsg; ++sg) {
        float4 nv[8];
        if (sg + 1 < nsg) {   // prefetch next super-group's sim rows
            const float* nb2 = gsim + (size_t)(8 * (sg + 1)) * MM;
#pragma unroll
            for (int r = 0; r < 8; r++)
                nv[r] = *reinterpret_cast<const float4*>(nb2 + (size_t)r * MM);
        }
        int qa = 2 * sg, qb = 2 * sg + 1;
        // ---- quad A (rows 8sg+1 .. 8sg+4) ----
        if (b != 0) { while (!inc_ready(pA)) pA = ldv4(bnd + qa); }
        int i = 8 * sg + 1;
        float4 outA;
        outA.x = dp_row(lane, i + 0, dropline, sv[0], pA.x, prev0, prev1, prev2, prev3, bcar, decp);
        outA.y = dp_row(lane, i + 1, dropline, sv[1], pA.y, prev0, prev1, prev2, prev3, bcar, decp);
        outA.z = dp_row(lane, i + 2, dropline, sv[2], pA.z, prev0, prev1, prev2, prev3, bcar, decp);
        outA.w = dp_row(lane, i + 3, dropline, sv[3], pA.w, prev0, prev1, prev2, prev3, bcar, decp);

        // peek next super-group's quads BEFORE any publish store (LD precedes ST)
        float4 qAn, qBn;
        qAn.x = qAn.y = qAn.z = qAn.w = 0.f;
        qBn.x = qBn.y = qBn.z = qBn.w = 0.f;
        bool need = (b != 0) && (sg + 1 < nsg);
        if (need) { qAn = ldv4(bnd + qa + 2); qBn = ldv4(bnd + qb + 2); }

        if (lane == 31 && b < NB - 1)
            stv4(&g_bound2[(size_t)(b + 1) * NG + qa], outA);

        // ---- quad B (rows 8sg+5 .. 8sg+8) ----
        if (b != 0) { while (!inc_ready(pB)) pB = ldv4(bnd + qb); }
        float4 outB;
        outB.x = dp_row(lane, i + 4, dropline, sv[4], pB.x, prev0, prev1, prev2, prev3, bcar, decp);
        outB.y = dp_row(lane, i + 5, dropline, sv[5], pB.y, prev0, prev1, prev2, prev3, bcar, decp);
        outB.z = dp_row(lane, i + 6, dropline, sv[6], pB.z, prev0, prev1, prev2, prev3, bcar, decp);
        outB.w = dp_row(lane, i + 7, dropline, sv[7], pB.w, prev0, prev1, prev2, prev3, bcar, decp);

        if (lane == 31 && b < NB - 1)
            stv4(&g_bound2[(size_t)(b + 1) * NG + qb], outB);

        pA = qAn; pB = qBn;
#pragma unroll
        for (int r = 0; r < 8; r++) sv[r] = nv[r];
    }
}

// ---------------- traceback: 448-row tiles, u64 nibble repack, left-run skipping ----------------
__device__ __forceinline__ unsigned nib_compact(unsigned long long x) {
    x &= 0x0F0F0F0F0F0F0F0Full;
    x = (x | (x >> 4))  & 0x00FF00FF00FF00FFull;
    x = (x | (x >> 8))  & 0x0000FFFF0000FFFFull;
    x = (x | (x >> 16));
    return (unsigned)x;
}

__global__ void traceback(float* __restrict__ out) {
    __shared__ uint2    s_du[TBR * 8];
    __shared__ unsigned s_c[TBR * 8];
    __shared__ int s_ij[2];
    int t = threadIdx.x;    // 256 threads
    int i = NN, j = MM;
    while (i > 0 && j > 0) {
        int ilo = (i - (TBR - 1) > 1) ? (i - (TBR - 1)) : 1;
        int jbhi = (j - 1) >> 7;                       // 128-col strip of current jj
        int jblo = (jbhi - 1 > 0) ? (jbhi - 1) : 0;    // stage 2 strips
        int rows = i - ilo + 1;
        for (int idx = t; idx < rows * 8; idx += 256) {
            int r = idx >> 3, wq = idx & 7;            // natural word 0..7 across 2 strips
            int strip = jblo + (wq >> 2), w4 = wq & 3;
            size_t boff = (size_t)strip * ((size_t)NN * 32)
                        + (size_t)(ilo - 1 + r) * 32 + (size_t)w4 * 8;
            unsigned long long Bv = *reinterpret_cast<const unsigned long long*>(&g_dec[boff]);
            unsigned dw = nib_compact(Bv);
            unsigned uw = nib_compact(Bv >> 4);
            s_du[r * 8 + wq] = make_uint2(dw, uw);
            s_c[r * 8 + wq] = dw | uw;
        }
        __syncthreads();
        if (t == 0) {
            int jlo = jblo * 128 + 1;                  // smallest j inside the staged strips
            while (i >= ilo && j >= jlo) {
                int jj = j - 1;
                int r = i - ilo;
                int w = (jj >> 5) - jblo * 4;          // 0..7
                int bit = jj & 31;
                uint2 du = s_du[r * 8 + w];
                if ((du.x >> bit) & 1u) {
                    out[(size_t)(i - 1) * MM + jj] = 1.0f; --i; --j;
                } else if ((du.y >> bit) & 1u) {
                    --i;
                } else {
                    unsigned m = s_c[r * 8 + w] & ((bit == 0) ? 0u : ((1u << bit) - 1u));
                    for (;;) {
                        if (m) { int nb = 31 - __clz(m); j = (jblo * 4 + w) * 32 + nb + 1; break; }
                        if (w == 0) { j = jlo - 1; break; }
                        --w;
                        m = s_c[r * 8 + w];
                    }
                }
            }
            s_ij[0] = i; s_ij[1] = j;
        }
        __syncthreads();
        i = s_ij[0]; j = s_ij[1];
        __syncthreads();
    }
}

// ---------------- launch ----------------
extern "C" void kernel_launch(void* const* d_in, const int* in_sizes, int n_in,
                              void* d_out, int out_size) {
    (void)in_sizes; (void)n_in; (void)out_size;
    const float* text  = (const float*)d_in[2];
    const float* event = (const float*)d_in[3];
    float* out = (float*)d_out;

    // gemm_nt is launch #4 for ncu (-s 5 -c 1 + 2 harness launches).
    init_state<<<256, 256>>>();
    normalize_rows<<<NN, 256>>>(text, 0);
    normalize_rows<<<MM, 256>>>(event, 1);
    gemm_nt<<<dim3(32, 16), 256>>>();
    for (int p = 0; p < 4; ++p) {
        int shift = 24 - 8 * p;
        hist_pass<<<2048, 256>>>(shift);
        select_pass<<<1, 256>>>(shift, p == 3 ? 1 : 0);
    }
    fill_zero4<<<2048, 256>>>((float4*)out, (size_t)NN * MM / 4);
    dp_kernel<<<NB, 32>>>(NN);
    traceback<<<1, 256>>>(out);
}